// round 11
// baseline (speedup 1.0000x reference)
#include <cuda_runtime.h>
#include <cstdint>

// Shapes (fixed): B=8, S=4096, E=512 -> M=32768, N=K=512
#define M_TOT 32768
#define N_TOT 512
#define K_TOT 512

#define BM 128
#define BN 128
#define BK 32
#define NTH 128               // 4 warps, 2(m) x 2(n), warp tile 64x64
#define NCH (K_TOT / BK)      // 16
#define NSTAGE 3

// smem: per stage A[128][36] + B[128][36] floats (pad 4 -> conflict-free LDSM)
#define ROWF 36
#define B_OFF (128 * ROWF)        // floats
#define STG_F (2 * 128 * ROWF)    // 9216 floats / stage
#define SMEM_BYTES (NSTAGE * STG_F * 4)   // 110592 B -> 2 CTAs/SM

// ---------------- scratch (device globals: sanctioned no-alloc path) ----------
__device__ float g_V [(size_t)M_TOT * N_TOT];
__device__ float g_Vc[(size_t)M_TOT * N_TOT];
__device__ float g_Wa[(size_t)N_TOT * K_TOT];   // pre-rounded input_weights
__device__ float g_Wb[(size_t)N_TOT * K_TOT];   // pre-rounded out_proj_w

__device__ __forceinline__ uint32_t f2tf(float x) {
    uint32_t u;
    asm("cvt.rna.tf32.f32 %0, %1;" : "=r"(u) : "f"(x));
    return u;
}
__device__ __forceinline__ uint32_t smem_u32(const void* p) {
    uint32_t a;
    asm("{ .reg .u64 t; cvta.to.shared.u64 t, %1; cvt.u32.u64 %0, t; }" : "=r"(a) : "l"(p));
    return a;
}
__device__ __forceinline__ void cp16(uint32_t saddr, const void* gptr) {
    asm volatile("cp.async.cg.shared.global [%0], [%1], 16;"
                 :: "r"(saddr), "l"(gptr) : "memory");
}
// ldmatrix x4 on 8x4-float tiles (viewed as 8x8 b16): delivers tf32 fragments.
__device__ __forceinline__ void ldsm4(uint32_t* r, uint32_t addr) {
    asm volatile("ldmatrix.sync.aligned.m8n8.x4.shared.b16 {%0,%1,%2,%3}, [%4];"
                 : "=r"(r[0]), "=r"(r[1]), "=r"(r[2]), "=r"(r[3]) : "r"(addr));
}
__device__ __forceinline__ void mma8(float* c, const uint32_t* a,
                                     uint32_t b0, uint32_t b1) {
    asm volatile(
        "mma.sync.aligned.m16n8k8.row.col.f32.tf32.tf32.f32 "
        "{%0,%1,%2,%3}, {%4,%5,%6,%7}, {%8,%9}, {%0,%1,%2,%3};"
        : "+f"(c[0]), "+f"(c[1]), "+f"(c[2]), "+f"(c[3])
        : "r"(a[0]), "r"(a[1]), "r"(a[2]), "r"(a[3]), "r"(b0), "r"(b1));
}

// C[m,n] = sum_k A[m,k]*B[n,k]; B tf32-prerounded; ROUND_A rounds A fragments.
// 64x64 warp tiles, register double-buffered LDSM fragments. SAFETY INVARIANT:
// smem written by cp.async is only read after wait_group + __syncthreads
// (wait_group alone orders only the calling thread's copies).
template <bool ROUND_A>
__global__ __launch_bounds__(NTH, 2)
void gemm_pipe(const float* __restrict__ A,
               const float* __restrict__ B,
               float* __restrict__ C)
{
    extern __shared__ float sm[];
    const uint32_t sb = smem_u32(sm);
    const int tid  = threadIdx.x;
    const int wid  = tid >> 5;
    const int lane = tid & 31;
    const int wm   = wid >> 1;     // 0..1 -> 64-row stripe
    const int wn   = wid & 1;      // 0..1 -> 64-col stripe
    const int lr   = lane >> 2;
    const int lc   = lane & 3;
    const int bm   = blockIdx.y * BM;
    const int bn   = blockIdx.x * BN;

    const float4* Ag = (const float4*)(A + (size_t)bm * K_TOT);
    const float4* Bg = (const float4*)(B + (size_t)bn * K_TOT);

    // per-lane LDSM byte offsets (8-lane groups -> one 8x4-float matrix)
    const uint32_t laneA = ((((lane >> 3) & 1) * 8 + (lane & 7)) * ROWF
                            + ((lane >> 4) * 4)) * 4u;
    const uint32_t laneB = (((lane >> 4) * 8 + (lane & 7)) * ROWF
                            + (((lane >> 3) & 1) * 4)) * 4u;

    auto issue = [&](int c, int s) {
        const uint32_t sa  = sb + (uint32_t)(s * STG_F) * 4u;
        const uint32_t sbB = sa + (uint32_t)B_OFF * 4u;
        #pragma unroll
        for (int i = 0; i < 8; i++) {
            int f = tid + i * NTH, m = f >> 3, q = f & 7;
            cp16(sa + (uint32_t)(m * ROWF + q * 4) * 4u,
                 Ag + (size_t)m * (K_TOT / 4) + c * 8 + q);
        }
        #pragma unroll
        for (int i = 0; i < 8; i++) {
            int f = tid + i * NTH, n = f >> 3, q = f & 7;
            cp16(sbB + (uint32_t)(n * ROWF + q * 4) * 4u,
                 Bg + (size_t)n * (K_TOT / 4) + c * 8 + q);
        }
        asm volatile("cp.async.commit_group;" ::: "memory");
    };

    // double-buffered fragments
    uint32_t afr[2][4][4], bfr[2][4][4];

    auto ldfrag = [&](int c, int ks, int buf) {
        const uint32_t sA = sb + (uint32_t)((c % NSTAGE) * STG_F) * 4u;
        const uint32_t sB = sA + (uint32_t)B_OFF * 4u;
        const uint32_t aBase = sA + (uint32_t)(wm * 64 * ROWF) * 4u + laneA;
        const uint32_t bBase = sB + (uint32_t)(wn * 64 * ROWF) * 4u + laneB;
        const uint32_t kbb = (uint32_t)ks * 32u;
        #pragma unroll
        for (int mt = 0; mt < 4; mt++)
            ldsm4(afr[buf][mt], aBase + (uint32_t)(mt * 16 * ROWF) * 4u + kbb);
        #pragma unroll
        for (int p = 0; p < 4; p++)
            ldsm4(bfr[buf][p], bBase + (uint32_t)(p * 16 * ROWF) * 4u + kbb);
        if (ROUND_A) {
            #pragma unroll
            for (int mt = 0; mt < 4; mt++)
                #pragma unroll
                for (int j = 0; j < 4; j++)
                    afr[buf][mt][j] = f2tf(__uint_as_float(afr[buf][mt][j]));
        }
    };

    float acc[4][8][4];
    #pragma unroll
    for (int a = 0; a < 4; a++)
        #pragma unroll
        for (int b = 0; b < 8; b++)
            #pragma unroll
            for (int r = 0; r < 4; r++) acc[a][b][r] = 0.0f;

    auto domma = [&](int buf) {
        #pragma unroll
        for (int mt = 0; mt < 4; mt++) {
            #pragma unroll
            for (int nt = 0; nt < 8; nt++) {
                uint32_t b0 = bfr[buf][nt >> 1][(nt & 1) * 2 + 0];
                uint32_t b1 = bfr[buf][nt >> 1][(nt & 1) * 2 + 1];
                mma8(acc[mt][nt], afr[buf][mt], b0, b1);
            }
        }
    };

    // prologue: g0,g1 in flight; make stage0 visible to ALL threads, then g2
    issue(0, 0);
    issue(1, 1);
    asm volatile("cp.async.wait_group 1;" ::: "memory");   // my g0 done
    __syncthreads();                                       // everyone's g0 visible
    issue(2, 2);
    ldfrag(0, 0, 0);
    int pb = 0;

    for (int c = 0; c < NCH; c++) {
        // intra-chunk: prefetch fragments ks+1 while MMA-ing ks (stage already safe)
        #pragma unroll
        for (int kk = 0; kk < 4; kk++) {
            if (kk < 3) ldfrag(c, kk + 1, pb ^ 1);
            domma(pb);
            pb ^= 1;
        }
        if (c + 1 < NCH) {
            // committed groups: 0..c+2; <=1 outstanding => my g(c+1) done
            asm volatile("cp.async.wait_group 1;" ::: "memory");
            __syncthreads();            // all threads' g(c+1) visible; stage c%3 free
            if (c + 3 < NCH) issue(c + 3, (c + 3) % NSTAGE);
            else asm volatile("cp.async.commit_group;" ::: "memory");
            ldfrag(c + 1, 0, pb ^ 1);   // safe: after barrier
            pb ^= 1;                    // buffer holding ks=0 of next chunk
        }
    }

    // ---- epilogue ----
    #pragma unroll
    for (int mt = 0; mt < 4; mt++) {
        int m = bm + wm * 64 + mt * 16 + lr;
        float* crow = C + (size_t)m * N_TOT + bn + wn * 64;
        #pragma unroll
        for (int nt = 0; nt < 8; nt++) {
            int nf = nt * 8 + lc * 2;
            *(float2*)(crow + nf) = make_float2(acc[mt][nt][0], acc[mt][nt][1]);
            *(float2*)(crow + nf + (size_t)8 * N_TOT) =
                make_float2(acc[mt][nt][2], acc[mt][nt][3]);
        }
    }
}

// ---------------- tf32 (rna) pre-round, vectorized (weights only) ------------
__global__ void round_kernel(const float4* __restrict__ w, float4* __restrict__ o)
{
    int i = blockIdx.x * 256 + threadIdx.x;
    float4 v = w[i];
    o[i] = make_float4(__uint_as_float(f2tf(v.x)), __uint_as_float(f2tf(v.y)),
                       __uint_as_float(f2tf(v.z)), __uint_as_float(f2tf(v.w)));
}

// ---- 5-tap Gaussian window, per-head shift {0,-1,+1,0}x2; output tf32-rounded
__global__ void conv_kernel(const float4* __restrict__ V, float4* __restrict__ Vc)
{
    int idx = blockIdx.x * blockDim.x + threadIdx.x;   // M_TOT*128 threads
    int c4  = idx & 127;
    int m   = idx >> 7;
    int s   = m & 4095;
    int mb0 = m - s;
    int hm  = (c4 >> 4) & 3;
    int shift = (hm == 1) ? -1 : ((hm == 2) ? 1 : 0);

    const float F[5] = {0.05399096651318806f, 0.24197072451914337f,
                        0.3989422804014327f,  0.24197072451914337f,
                        0.05399096651318806f};

    float ax = 0.f, ay = 0.f, az = 0.f, aw = 0.f;
    #pragma unroll
    for (int j = 0; j < 5; j++) {
        int ss = s + shift + j - 2;
        if (ss >= 0 && ss < 4096) {
            float4 v = V[(size_t)(mb0 + ss) * 128 + c4];
            ax += F[j] * v.x; ay += F[j] * v.y; az += F[j] * v.z; aw += F[j] * v.w;
        }
    }
    Vc[idx] = make_float4(__uint_as_float(f2tf(ax)), __uint_as_float(f2tf(ay)),
                          __uint_as_float(f2tf(az)), __uint_as_float(f2tf(aw)));
}

// ---------------- launcher ----------------
extern "C" void kernel_launch(void* const* d_in, const int* in_sizes, int n_in,
                              void* d_out, int out_size)
{
    const float* values = (const float*)d_in[0];
    const float* win    = (const float*)d_in[3];
    const float* wout   = (const float*)d_in[4];
    float*       out    = (float*)d_out;

    float *pV, *pVc, *pWa, *pWb;
    cudaGetSymbolAddress((void**)&pV,  g_V);
    cudaGetSymbolAddress((void**)&pVc, g_Vc);
    cudaGetSymbolAddress((void**)&pWa, g_Wa);
    cudaGetSymbolAddress((void**)&pWb, g_Wb);

    cudaFuncSetAttribute(gemm_pipe<true>,
                         cudaFuncAttributeMaxDynamicSharedMemorySize, SMEM_BYTES);
    cudaFuncSetAttribute(gemm_pipe<false>,
                         cudaFuncAttributeMaxDynamicSharedMemorySize, SMEM_BYTES);

    dim3 grid(N_TOT / BN, M_TOT / BM);   // (4, 256)

    round_kernel<<<256, 256>>>((const float4*)win,  (float4*)pWa);
    round_kernel<<<256, 256>>>((const float4*)wout, (float4*)pWb);
    gemm_pipe<true ><<<grid, NTH, SMEM_BYTES>>>(values, pWa, pV);
    conv_kernel<<<(M_TOT * 128) / 256, 256>>>((const float4*)pV, (float4*)pVc);
    gemm_pipe<false><<<grid, NTH, SMEM_BYTES>>>(pVc, pWb, out);
}

// round 12
// speedup vs baseline: 1.6312x; 1.6312x over previous
#include <cuda_runtime.h>
#include <cstdint>

// Shapes (fixed): B=8, S=4096, E=512 -> M=32768, N=K=512
#define M_TOT 32768
#define N_TOT 512
#define K_TOT 512

#define BM 128
#define BN 64
#define BK 32
#define NTH 128               // 4 warps, 2(m) x 2(n), warp tile 64x32
#define NCH (K_TOT / BK)      // 16
#define NSTAGE 2

// smem: per stage A[128][36] + B[64][36] floats (pad 4 -> conflict-free LDSM)
#define ROWF 36
#define B_OFF (128 * ROWF)                // floats
#define STG_F ((128 + 64) * ROWF)         // 6912 floats / stage
#define SMEM_BYTES (NSTAGE * STG_F * 4)   // 55296 B -> 3 CTAs/SM

// ---------------- scratch (device globals: sanctioned no-alloc path) ----------
__device__ float g_V [(size_t)M_TOT * N_TOT];
__device__ float g_Vc[(size_t)M_TOT * N_TOT];
__device__ float g_Wa[(size_t)N_TOT * K_TOT];   // pre-rounded input_weights
__device__ float g_Wb[(size_t)N_TOT * K_TOT];   // pre-rounded out_proj_w

__device__ __forceinline__ uint32_t f2tf(float x) {
    uint32_t u;
    asm("cvt.rna.tf32.f32 %0, %1;" : "=r"(u) : "f"(x));
    return u;
}
__device__ __forceinline__ uint32_t smem_u32(const void* p) {
    uint32_t a;
    asm("{ .reg .u64 t; cvta.to.shared.u64 t, %1; cvt.u32.u64 %0, t; }" : "=r"(a) : "l"(p));
    return a;
}
__device__ __forceinline__ void cp16(uint32_t saddr, const void* gptr) {
    asm volatile("cp.async.cg.shared.global [%0], [%1], 16;"
                 :: "r"(saddr), "l"(gptr) : "memory");
}
// ldmatrix x4 on 8x4-float tiles (viewed as 8x8 b16): delivers tf32 fragments.
__device__ __forceinline__ void ldsm4(uint32_t* r, uint32_t addr) {
    asm volatile("ldmatrix.sync.aligned.m8n8.x4.shared.b16 {%0,%1,%2,%3}, [%4];"
                 : "=r"(r[0]), "=r"(r[1]), "=r"(r[2]), "=r"(r[3]) : "r"(addr));
}
__device__ __forceinline__ void mma8(float* c, const uint32_t* a,
                                     uint32_t b0, uint32_t b1) {
    asm volatile(
        "mma.sync.aligned.m16n8k8.row.col.f32.tf32.tf32.f32 "
        "{%0,%1,%2,%3}, {%4,%5,%6,%7}, {%8,%9}, {%0,%1,%2,%3};"
        : "+f"(c[0]), "+f"(c[1]), "+f"(c[2]), "+f"(c[3])
        : "r"(a[0]), "r"(a[1]), "r"(a[2]), "r"(a[3]), "r"(b0), "r"(b1));
}

// C[m,n] = sum_k A[m,k]*B[n,k]; B tf32-prerounded; ROUND_A rounds A fragments.
// 64x32 warp tiles, 3 CTAs/SM, STATICALLY-NAMED double-buffered fragments
// (all register indices compile-time constant -> no local-memory demotion).
template <bool ROUND_A>
__global__ __launch_bounds__(NTH, 3)
void gemm_db(const float* __restrict__ A,
             const float* __restrict__ B,
             float* __restrict__ C)
{
    extern __shared__ float sm[];
    const uint32_t sb = smem_u32(sm);
    const int tid  = threadIdx.x;
    const int wid  = tid >> 5;
    const int lane = tid & 31;
    const int wm   = wid >> 1;     // 0..1 -> 64-row stripe
    const int wn   = wid & 1;      // 0..1 -> 32-col stripe
    const int lr   = lane >> 2;
    const int lc   = lane & 3;
    const int bm   = blockIdx.y * BM;
    const int bn   = blockIdx.x * BN;

    const float4* Ag = (const float4*)(A + (size_t)bm * K_TOT);
    const float4* Bg = (const float4*)(B + (size_t)bn * K_TOT);

    // per-lane LDSM byte offsets (8-lane groups -> one 8x4-float matrix)
    const uint32_t laneA = ((((lane >> 3) & 1) * 8 + (lane & 7)) * ROWF
                            + ((lane >> 4) * 4)) * 4u;
    const uint32_t laneB = (((lane >> 4) * 8 + (lane & 7)) * ROWF
                            + (((lane >> 3) & 1) * 4)) * 4u;

    auto issue = [&](int c) {
        const int s = c & 1;
        const uint32_t sa  = sb + (uint32_t)(s * STG_F) * 4u;
        const uint32_t sbB = sa + (uint32_t)B_OFF * 4u;
        #pragma unroll
        for (int i = 0; i < 8; i++) {              // A: 128 rows x 8 f4
            int f = tid + i * NTH, m = f >> 3, q = f & 7;
            cp16(sa + (uint32_t)(m * ROWF + q * 4) * 4u,
                 Ag + (size_t)m * (K_TOT / 4) + c * 8 + q);
        }
        #pragma unroll
        for (int i = 0; i < 4; i++) {              // B: 64 rows x 8 f4
            int f = tid + i * NTH, n = f >> 3, q = f & 7;
            cp16(sbB + (uint32_t)(n * ROWF + q * 4) * 4u,
                 Bg + (size_t)n * (K_TOT / 4) + c * 8 + q);
        }
        asm volatile("cp.async.commit_group;" ::: "memory");
    };

    // statically named double buffers (never dynamically indexed)
    uint32_t af0[4][4], bf0[2][4];
    uint32_t af1[4][4], bf1[2][4];

    float acc[4][4][4];
    #pragma unroll
    for (int a = 0; a < 4; a++)
        #pragma unroll
        for (int b = 0; b < 4; b++)
            #pragma unroll
            for (int r = 0; r < 4; r++) acc[a][b][r] = 0.0f;

    #define LDFRAG(c, ks, AF, BF)                                               \
        do {                                                                    \
            const uint32_t sA_ = sb + (uint32_t)(((c) & 1) * STG_F) * 4u;       \
            const uint32_t aB_ = sA_ + (uint32_t)(wm * 64 * ROWF) * 4u + laneA; \
            const uint32_t bB_ = sA_ + (uint32_t)B_OFF * 4u                     \
                                 + (uint32_t)(wn * 32 * ROWF) * 4u + laneB;     \
            const uint32_t kb_ = (uint32_t)(ks) * 32u;                          \
            _Pragma("unroll")                                                   \
            for (int mt = 0; mt < 4; mt++)                                      \
                ldsm4(AF[mt], aB_ + (uint32_t)(mt * 16 * ROWF) * 4u + kb_);     \
            _Pragma("unroll")                                                   \
            for (int p = 0; p < 2; p++)                                         \
                ldsm4(BF[p], bB_ + (uint32_t)(p * 16 * ROWF) * 4u + kb_);       \
            if (ROUND_A) {                                                      \
                _Pragma("unroll")                                               \
                for (int mt = 0; mt < 4; mt++)                                  \
                    _Pragma("unroll")                                           \
                    for (int j = 0; j < 4; j++)                                 \
                        AF[mt][j] = f2tf(__uint_as_float(AF[mt][j]));           \
            }                                                                   \
        } while (0)

    #define DOMMA(AF, BF)                                                       \
        do {                                                                    \
            _Pragma("unroll")                                                   \
            for (int mt = 0; mt < 4; mt++) {                                    \
                _Pragma("unroll")                                               \
                for (int nt = 0; nt < 4; nt++) {                                \
                    uint32_t b0_ = BF[nt >> 1][(nt & 1) * 2 + 0];               \
                    uint32_t b1_ = BF[nt >> 1][(nt & 1) * 2 + 1];               \
                    mma8(acc[mt][nt], AF[mt], b0_, b1_);                        \
                }                                                               \
            }                                                                   \
        } while (0)

    issue(0);   // group 0 -> stage 0

    for (int c = 0; c < NCH; c++) {
        __syncthreads();                       // WAR: stage (c+1)&1 free to overwrite
        if (c + 1 < NCH) {
            issue(c + 1);                      // group c+1 -> stage (c+1)&1
            asm volatile("cp.async.wait_group 1;" ::: "memory");  // g_c done
        } else {
            asm volatile("cp.async.wait_group 0;" ::: "memory");
        }
        __syncthreads();                       // publish g_c to all threads

        // ping-pong over 4 k-slices, all buffer names static
        LDFRAG(c, 0, af0, bf0);
        LDFRAG(c, 1, af1, bf1);
        DOMMA(af0, bf0);
        LDFRAG(c, 2, af0, bf0);
        DOMMA(af1, bf1);
        LDFRAG(c, 3, af1, bf1);
        DOMMA(af0, bf0);
        DOMMA(af1, bf1);
    }

    // ---- epilogue ----
    #pragma unroll
    for (int mt = 0; mt < 4; mt++) {
        int m = bm + wm * 64 + mt * 16 + lr;
        float* crow = C + (size_t)m * N_TOT + bn + wn * 32;
        #pragma unroll
        for (int nt = 0; nt < 4; nt++) {
            int nf = nt * 8 + lc * 2;
            *(float2*)(crow + nf) = make_float2(acc[mt][nt][0], acc[mt][nt][1]);
            *(float2*)(crow + nf + (size_t)8 * N_TOT) =
                make_float2(acc[mt][nt][2], acc[mt][nt][3]);
        }
    }
    #undef LDFRAG
    #undef DOMMA
}

// ---------------- tf32 (rna) pre-round, vectorized (weights only) ------------
__global__ void round_kernel(const float4* __restrict__ w, float4* __restrict__ o)
{
    int i = blockIdx.x * 256 + threadIdx.x;
    float4 v = w[i];
    o[i] = make_float4(__uint_as_float(f2tf(v.x)), __uint_as_float(f2tf(v.y)),
                       __uint_as_float(f2tf(v.z)), __uint_as_float(f2tf(v.w)));
}

// ---- 5-tap Gaussian window, per-head shift {0,-1,+1,0}x2; output tf32-rounded
__global__ void conv_kernel(const float4* __restrict__ V, float4* __restrict__ Vc)
{
    int idx = blockIdx.x * blockDim.x + threadIdx.x;   // M_TOT*128 threads
    int c4  = idx & 127;
    int m   = idx >> 7;
    int s   = m & 4095;
    int mb0 = m - s;
    int hm  = (c4 >> 4) & 3;
    int shift = (hm == 1) ? -1 : ((hm == 2) ? 1 : 0);

    const float F[5] = {0.05399096651318806f, 0.24197072451914337f,
                        0.3989422804014327f,  0.24197072451914337f,
                        0.05399096651318806f};

    float ax = 0.f, ay = 0.f, az = 0.f, aw = 0.f;
    #pragma unroll
    for (int j = 0; j < 5; j++) {
        int ss = s + shift + j - 2;
        if (ss >= 0 && ss < 4096) {
            float4 v = V[(size_t)(mb0 + ss) * 128 + c4];
            ax += F[j] * v.x; ay += F[j] * v.y; az += F[j] * v.z; aw += F[j] * v.w;
        }
    }
    Vc[idx] = make_float4(__uint_as_float(f2tf(ax)), __uint_as_float(f2tf(ay)),
                          __uint_as_float(f2tf(az)), __uint_as_float(f2tf(aw)));
}

// ---------------- launcher ----------------
extern "C" void kernel_launch(void* const* d_in, const int* in_sizes, int n_in,
                              void* d_out, int out_size)
{
    const float* values = (const float*)d_in[0];
    const float* win    = (const float*)d_in[3];
    const float* wout   = (const float*)d_in[4];
    float*       out    = (float*)d_out;

    float *pV, *pVc, *pWa, *pWb;
    cudaGetSymbolAddress((void**)&pV,  g_V);
    cudaGetSymbolAddress((void**)&pVc, g_Vc);
    cudaGetSymbolAddress((void**)&pWa, g_Wa);
    cudaGetSymbolAddress((void**)&pWb, g_Wb);

    cudaFuncSetAttribute(gemm_db<true>,
                         cudaFuncAttributeMaxDynamicSharedMemorySize, SMEM_BYTES);
    cudaFuncSetAttribute(gemm_db<false>,
                         cudaFuncAttributeMaxDynamicSharedMemorySize, SMEM_BYTES);

    dim3 grid(N_TOT / BN, M_TOT / BM);   // (8, 256)

    round_kernel<<<256, 256>>>((const float4*)win,  (float4*)pWa);
    round_kernel<<<256, 256>>>((const float4*)wout, (float4*)pWb);
    gemm_db<true ><<<grid, NTH, SMEM_BYTES>>>(values, pWa, pV);
    conv_kernel<<<(M_TOT * 128) / 256, 256>>>((const float4*)pV, (float4*)pVc);
    gemm_db<false><<<grid, NTH, SMEM_BYTES>>>(pVc, pWb, out);
}

// round 13
// speedup vs baseline: 1.8484x; 1.1332x over previous
#include <cuda_runtime.h>
#include <cstdint>

// Shapes (fixed): B=8, S=4096, E=512 -> M=32768, N=K=512
#define M_TOT 32768
#define N_TOT 512
#define K_TOT 512

#define BM 128
#define BN 128
#define BK 32
#define NTH 128               // 4 warps, 2(m) x 2(n), warp tile 64x64
#define NCH (K_TOT / BK)      // 16
#define NSTAGE 3

// smem: per stage A[128][36] + B[128][36] floats (pad 4 -> conflict-free LDSM)
#define ROWF 36
#define B_OFF (128 * ROWF)        // floats
#define STG_F (2 * 128 * ROWF)    // 9216 floats / stage
#define SMEM_BYTES (NSTAGE * STG_F * 4)   // 110592 B -> 2 CTAs/SM

// ---------------- scratch (device globals: sanctioned no-alloc path) ----------
__device__ float g_V [(size_t)M_TOT * N_TOT];
__device__ float g_Vc[(size_t)M_TOT * N_TOT];
__device__ float g_Wa[(size_t)N_TOT * K_TOT];   // pre-rounded input_weights
__device__ float g_Wb[(size_t)N_TOT * K_TOT];   // pre-rounded out_proj_w

__device__ __forceinline__ uint32_t f2tf(float x) {
    uint32_t u;
    asm("cvt.rna.tf32.f32 %0, %1;" : "=r"(u) : "f"(x));
    return u;
}
__device__ __forceinline__ uint32_t smem_u32(const void* p) {
    uint32_t a;
    asm("{ .reg .u64 t; cvta.to.shared.u64 t, %1; cvt.u32.u64 %0, t; }" : "=r"(a) : "l"(p));
    return a;
}
__device__ __forceinline__ void cp16(uint32_t saddr, const void* gptr) {
    asm volatile("cp.async.cg.shared.global [%0], [%1], 16;"
                 :: "r"(saddr), "l"(gptr) : "memory");
}
// ldmatrix x4 on 8x4-float tiles (viewed as 8x8 b16): delivers tf32 fragments.
__device__ __forceinline__ void ldsm4(uint32_t* r, uint32_t addr) {
    asm volatile("ldmatrix.sync.aligned.m8n8.x4.shared.b16 {%0,%1,%2,%3}, [%4];"
                 : "=r"(r[0]), "=r"(r[1]), "=r"(r[2]), "=r"(r[3]) : "r"(addr));
}
__device__ __forceinline__ void mma8(float* c, const uint32_t* a,
                                     uint32_t b0, uint32_t b1) {
    asm volatile(
        "mma.sync.aligned.m16n8k8.row.col.f32.tf32.tf32.f32 "
        "{%0,%1,%2,%3}, {%4,%5,%6,%7}, {%8,%9}, {%0,%1,%2,%3};"
        : "+f"(c[0]), "+f"(c[1]), "+f"(c[2]), "+f"(c[3])
        : "r"(a[0]), "r"(a[1]), "r"(a[2]), "r"(a[3]), "r"(b0), "r"(b1));
}

// C[m,n] = sum_k A[m,k]*B[n,k]; B tf32-prerounded; ROUND_A rounds A fragments.
// 64x64 warp tiles, 2 CTAs/SM, STATICALLY-NAMED double-buffered fragments.
// Safety invariant: smem written by cp.async is read only after
// wait_group + __syncthreads (wait orders only the calling thread's copies).
template <bool ROUND_A>
__global__ __launch_bounds__(NTH, 2)
void gemm_db2(const float* __restrict__ A,
              const float* __restrict__ B,
              float* __restrict__ C)
{
    extern __shared__ float sm[];
    const uint32_t sb = smem_u32(sm);
    const int tid  = threadIdx.x;
    const int wid  = tid >> 5;
    const int lane = tid & 31;
    const int wm   = wid >> 1;     // 0..1 -> 64-row stripe
    const int wn   = wid & 1;      // 0..1 -> 64-col stripe
    const int lr   = lane >> 2;
    const int lc   = lane & 3;
    const int bm   = blockIdx.y * BM;
    const int bn   = blockIdx.x * BN;

    const float4* Ag = (const float4*)(A + (size_t)bm * K_TOT);
    const float4* Bg = (const float4*)(B + (size_t)bn * K_TOT);

    // per-lane LDSM byte offsets (8-lane groups -> one 8x4-float matrix)
    const uint32_t laneA = ((((lane >> 3) & 1) * 8 + (lane & 7)) * ROWF
                            + ((lane >> 4) * 4)) * 4u;
    const uint32_t laneB = (((lane >> 4) * 8 + (lane & 7)) * ROWF
                            + (((lane >> 3) & 1) * 4)) * 4u;

    auto issue = [&](int c) {
        const int s = c % NSTAGE;
        const uint32_t sa  = sb + (uint32_t)(s * STG_F) * 4u;
        const uint32_t sbB = sa + (uint32_t)B_OFF * 4u;
        #pragma unroll
        for (int i = 0; i < 8; i++) {              // A: 128 rows x 8 f4
            int f = tid + i * NTH, m = f >> 3, q = f & 7;
            cp16(sa + (uint32_t)(m * ROWF + q * 4) * 4u,
                 Ag + (size_t)m * (K_TOT / 4) + c * 8 + q);
        }
        #pragma unroll
        for (int i = 0; i < 8; i++) {              // B: 128 rows x 8 f4
            int f = tid + i * NTH, n = f >> 3, q = f & 7;
            cp16(sbB + (uint32_t)(n * ROWF + q * 4) * 4u,
                 Bg + (size_t)n * (K_TOT / 4) + c * 8 + q);
        }
        asm volatile("cp.async.commit_group;" ::: "memory");
    };

    // statically named double buffers (never dynamically indexed)
    uint32_t af0[4][4], bf0[4][4];
    uint32_t af1[4][4], bf1[4][4];

    float acc[4][8][4];
    #pragma unroll
    for (int a = 0; a < 4; a++)
        #pragma unroll
        for (int b = 0; b < 8; b++)
            #pragma unroll
            for (int r = 0; r < 4; r++) acc[a][b][r] = 0.0f;

    #define LDFRAG(c, ks, AF, BF)                                               \
        do {                                                                    \
            const uint32_t sA_ = sb + (uint32_t)(((c) % NSTAGE) * STG_F) * 4u;  \
            const uint32_t aB_ = sA_ + (uint32_t)(wm * 64 * ROWF) * 4u + laneA; \
            const uint32_t bB_ = sA_ + (uint32_t)B_OFF * 4u                     \
                                 + (uint32_t)(wn * 64 * ROWF) * 4u + laneB;     \
            const uint32_t kb_ = (uint32_t)(ks) * 32u;                          \
            _Pragma("unroll")                                                   \
            for (int mt = 0; mt < 4; mt++)                                      \
                ldsm4(AF[mt], aB_ + (uint32_t)(mt * 16 * ROWF) * 4u + kb_);     \
            _Pragma("unroll")                                                   \
            for (int p = 0; p < 4; p++)                                         \
                ldsm4(BF[p], bB_ + (uint32_t)(p * 16 * ROWF) * 4u + kb_);       \
            if (ROUND_A) {                                                      \
                _Pragma("unroll")                                               \
                for (int mt = 0; mt < 4; mt++)                                  \
                    _Pragma("unroll")                                           \
                    for (int j = 0; j < 4; j++)                                 \
                        AF[mt][j] = f2tf(__uint_as_float(AF[mt][j]));           \
            }                                                                   \
        } while (0)

    #define DOMMA(AF, BF)                                                       \
        do {                                                                    \
            _Pragma("unroll")                                                   \
            for (int mt = 0; mt < 4; mt++) {                                    \
                _Pragma("unroll")                                               \
                for (int nt = 0; nt < 8; nt++) {                                \
                    uint32_t b0_ = BF[nt >> 1][(nt & 1) * 2 + 0];               \
                    uint32_t b1_ = BF[nt >> 1][(nt & 1) * 2 + 1];               \
                    mma8(acc[mt][nt], AF[mt], b0_, b1_);                        \
                }                                                               \
            }                                                                   \
        } while (0)

    // prologue: g0,g1 in flight; publish stage0, then g2 and first fragments
    issue(0);
    issue(1);
    asm volatile("cp.async.wait_group 1;" ::: "memory");   // my g0 done
    __syncthreads();                                       // everyone's g0 visible
    issue(2);
    LDFRAG(0, 0, af0, bf0);

    for (int c = 0; c < NCH; c++) {
        // intra-chunk ping-pong: prefetch ks+1 while MMA-ing ks
        LDFRAG(c, 1, af1, bf1);  DOMMA(af0, bf0);
        LDFRAG(c, 2, af0, bf0);  DOMMA(af1, bf1);
        LDFRAG(c, 3, af1, bf1);  DOMMA(af0, bf0);
        if (c + 1 < NCH) {
            // committed: 0..c+2; <=1 outstanding => g(c+1) done (mine)
            asm volatile("cp.async.wait_group 1;" ::: "memory");
            __syncthreads();           // publish g(c+1); stage c%3 reads done
            if (c + 3 < NCH) issue(c + 3);
            else asm volatile("cp.async.commit_group;" ::: "memory");
            LDFRAG(c + 1, 0, af0, bf0);   // safe: after barrier
            DOMMA(af1, bf1);              // ks3 of chunk c
        } else {
            DOMMA(af1, bf1);
        }
    }

    // ---- epilogue ----
    #pragma unroll
    for (int mt = 0; mt < 4; mt++) {
        int m = bm + wm * 64 + mt * 16 + lr;
        float* crow = C + (size_t)m * N_TOT + bn + wn * 64;
        #pragma unroll
        for (int nt = 0; nt < 8; nt++) {
            int nf = nt * 8 + lc * 2;
            *(float2*)(crow + nf) = make_float2(acc[mt][nt][0], acc[mt][nt][1]);
            *(float2*)(crow + nf + (size_t)8 * N_TOT) =
                make_float2(acc[mt][nt][2], acc[mt][nt][3]);
        }
    }
    #undef LDFRAG
    #undef DOMMA
}

// ---------------- tf32 (rna) pre-round, vectorized (weights only) ------------
__global__ void round_kernel(const float4* __restrict__ w, float4* __restrict__ o)
{
    int i = blockIdx.x * 256 + threadIdx.x;
    float4 v = w[i];
    o[i] = make_float4(__uint_as_float(f2tf(v.x)), __uint_as_float(f2tf(v.y)),
                       __uint_as_float(f2tf(v.z)), __uint_as_float(f2tf(v.w)));
}

// ---- 5-tap Gaussian window, per-head shift {0,-1,+1,0}x2; output tf32-rounded
__global__ void conv_kernel(const float4* __restrict__ V, float4* __restrict__ Vc)
{
    int idx = blockIdx.x * blockDim.x + threadIdx.x;   // M_TOT*128 threads
    int c4  = idx & 127;
    int m   = idx >> 7;
    int s   = m & 4095;
    int mb0 = m - s;
    int hm  = (c4 >> 4) & 3;
    int shift = (hm == 1) ? -1 : ((hm == 2) ? 1 : 0);

    const float F[5] = {0.05399096651318806f, 0.24197072451914337f,
                        0.3989422804014327f,  0.24197072451914337f,
                        0.05399096651318806f};

    float ax = 0.f, ay = 0.f, az = 0.f, aw = 0.f;
    #pragma unroll
    for (int j = 0; j < 5; j++) {
        int ss = s + shift + j - 2;
        if (ss >= 0 && ss < 4096) {
            float4 v = V[(size_t)(mb0 + ss) * 128 + c4];
            ax += F[j] * v.x; ay += F[j] * v.y; az += F[j] * v.z; aw += F[j] * v.w;
        }
    }
    Vc[idx] = make_float4(__uint_as_float(f2tf(ax)), __uint_as_float(f2tf(ay)),
                          __uint_as_float(f2tf(az)), __uint_as_float(f2tf(aw)));
}

// ---------------- launcher ----------------
extern "C" void kernel_launch(void* const* d_in, const int* in_sizes, int n_in,
                              void* d_out, int out_size)
{
    const float* values = (const float*)d_in[0];
    const float* win    = (const float*)d_in[3];
    const float* wout   = (const float*)d_in[4];
    float*       out    = (float*)d_out;

    float *pV, *pVc, *pWa, *pWb;
    cudaGetSymbolAddress((void**)&pV,  g_V);
    cudaGetSymbolAddress((void**)&pVc, g_Vc);
    cudaGetSymbolAddress((void**)&pWa, g_Wa);
    cudaGetSymbolAddress((void**)&pWb, g_Wb);

    cudaFuncSetAttribute(gemm_db2<true>,
                         cudaFuncAttributeMaxDynamicSharedMemorySize, SMEM_BYTES);
    cudaFuncSetAttribute(gemm_db2<false>,
                         cudaFuncAttributeMaxDynamicSharedMemorySize, SMEM_BYTES);

    dim3 grid(N_TOT / BN, M_TOT / BM);   // (4, 256)

    round_kernel<<<256, 256>>>((const float4*)win,  (float4*)pWa);
    round_kernel<<<256, 256>>>((const float4*)wout, (float4*)pWb);
    gemm_db2<true ><<<grid, NTH, SMEM_BYTES>>>(values, pWa, pV);
    conv_kernel<<<(M_TOT * 128) / 256, 256>>>((const float4*)pV, (float4*)pVc);
    gemm_db2<false><<<grid, NTH, SMEM_BYTES>>>(pVc, pWb, out);
}

// round 14
// speedup vs baseline: 2.8999x; 1.5689x over previous
#include <cuda_runtime.h>
#include <cuda_fp16.h>
#include <cstdint>

// Shapes (fixed): B=8, S=4096, E=512 -> M=32768, N=K=512
#define M_TOT 32768
#define N_TOT 512
#define K_TOT 512

#define BM 128
#define BN 128
#define BK 64                 // halves; 4 k-slices of k16 per chunk
#define NTH 128               // 4 warps, 2(m) x 2(n), warp tile 64x64
#define NCH (K_TOT / BK)      // 8
#define NSTAGE 3

// smem rows: 64 data halves (128B) + 8 pad halves (16B) = 144B/row.
// Row stride 144B = 36 banks ≡ 4 mod 32 -> 8 consecutive rows hit 8 distinct
// bank groups; LDSM conflict-free.
#define RB 144
#define B_OFF (128 * RB)                  // bytes: A region is 128 rows
#define STG_B (2 * 128 * RB)              // 36864 B / stage
#define SMEM_BYTES (NSTAGE * STG_B)       // 110592 B -> 2 CTAs/SM

// ---------------- scratch (device globals: sanctioned no-alloc path) ----------
__device__ __half g_Vh[(size_t)M_TOT * K_TOT];   // values in fp16
__device__ __half g_V [(size_t)M_TOT * N_TOT];   // GEMM1 out (fp16)
__device__ __half g_Vc[(size_t)M_TOT * N_TOT];   // conv out (fp16)
__device__ __half g_Wa[(size_t)N_TOT * K_TOT];   // input_weights fp16
__device__ __half g_Wb[(size_t)N_TOT * K_TOT];   // out_proj_w fp16

__device__ __forceinline__ uint32_t smem_u32(const void* p) {
    uint32_t a;
    asm("{ .reg .u64 t; cvta.to.shared.u64 t, %1; cvt.u32.u64 %0, t; }" : "=r"(a) : "l"(p));
    return a;
}
__device__ __forceinline__ void cp16(uint32_t saddr, const void* gptr) {
    asm volatile("cp.async.cg.shared.global [%0], [%1], 16;"
                 :: "r"(saddr), "l"(gptr) : "memory");
}
__device__ __forceinline__ void ldsm4(uint32_t* r, uint32_t addr) {
    asm volatile("ldmatrix.sync.aligned.m8n8.x4.shared.b16 {%0,%1,%2,%3}, [%4];"
                 : "=r"(r[0]), "=r"(r[1]), "=r"(r[2]), "=r"(r[3]) : "r"(addr));
}
// m16n8k16 fp16 -> fp32 acc
__device__ __forceinline__ void mma16(float* c, const uint32_t* a,
                                      uint32_t b0, uint32_t b1) {
    asm volatile(
        "mma.sync.aligned.m16n8k16.row.col.f32.f16.f16.f32 "
        "{%0,%1,%2,%3}, {%4,%5,%6,%7}, {%8,%9}, {%0,%1,%2,%3};"
        : "+f"(c[0]), "+f"(c[1]), "+f"(c[2]), "+f"(c[3])
        : "r"(a[0]), "r"(a[1]), "r"(a[2]), "r"(a[3]), "r"(b0), "r"(b1));
}

// C[m,n] = sum_k A[m,k]*B[n,k]; A,B fp16 row-major [.,K]; acc fp32.
// 64x64 warp tiles, 2 CTAs/SM, statically-named double-buffered fragments.
// Safety: cp.async-written smem read only after wait_group + __syncthreads.
template <bool HALF_OUT>
__global__ __launch_bounds__(NTH, 2)
void gemm_h16(const __half* __restrict__ A,
              const __half* __restrict__ B,
              void* __restrict__ Cv)
{
    extern __shared__ char sm[];
    const uint32_t sb = smem_u32(sm);
    const int tid  = threadIdx.x;
    const int wid  = tid >> 5;
    const int lane = tid & 31;
    const int wm   = wid >> 1;     // 0..1 -> 64-row stripe
    const int wn   = wid & 1;      // 0..1 -> 64-col stripe
    const int lr   = lane >> 2;
    const int lc   = lane & 3;
    const int bm   = blockIdx.y * BM;
    const int bn   = blockIdx.x * BN;
    const int grp  = lane >> 3;
    const int lr8  = lane & 7;

    const uint4* Ag = (const uint4*)(A + (size_t)bm * K_TOT);  // 8 halves/uint4
    const uint4* Bg = (const uint4*)(B + (size_t)bn * K_TOT);

    // LDSM lane addresses (byte offsets inside a warp tile region)
    // A (16x16 per mt): grp0 rows m0-7 @k0 | grp1 rows m8-15 @k0 |
    //                   grp2 rows m0-7 @k8(+16B) | grp3 rows m8-15 @k8
    const uint32_t laneA = (uint32_t)(((grp & 1) * 8 + lr8) * RB + (grp >> 1) * 16);
    // B (two n8x16): grp0 n0-7 @k0 | grp1 n0-7 @k8 | grp2 n8-15 @k0 | grp3 n8-15 @k8
    const uint32_t laneB = (uint32_t)(((grp >> 1) * 8 + lr8) * RB + (grp & 1) * 16);

    auto issue = [&](int c) {
        const int s = c % NSTAGE;
        const uint32_t sa  = sb + (uint32_t)(s * STG_B);
        const uint32_t sbB = sa + (uint32_t)B_OFF;
        #pragma unroll
        for (int i = 0; i < 8; i++) {              // A: 128 rows x 8 x 16B
            int f = tid + i * NTH, m = f >> 3, q = f & 7;
            cp16(sa + (uint32_t)(m * RB + q * 16),
                 Ag + (size_t)m * (K_TOT / 8) + c * 8 + q);
        }
        #pragma unroll
        for (int i = 0; i < 8; i++) {              // B: 128 rows x 8 x 16B
            int f = tid + i * NTH, n = f >> 3, q = f & 7;
            cp16(sbB + (uint32_t)(n * RB + q * 16),
                 Bg + (size_t)n * (K_TOT / 8) + c * 8 + q);
        }
        asm volatile("cp.async.commit_group;" ::: "memory");
    };

    // statically named double buffers
    uint32_t af0[4][4], bf0[4][4];
    uint32_t af1[4][4], bf1[4][4];

    float acc[4][8][4];
    #pragma unroll
    for (int a = 0; a < 4; a++)
        #pragma unroll
        for (int b = 0; b < 8; b++)
            #pragma unroll
            for (int r = 0; r < 4; r++) acc[a][b][r] = 0.0f;

    #define LDFRAG(c, ks, AF, BF)                                              \
        do {                                                                   \
            const uint32_t sA_ = sb + (uint32_t)(((c) % NSTAGE) * STG_B);      \
            const uint32_t aB_ = sA_ + (uint32_t)(wm * 64 * RB) + laneA;       \
            const uint32_t bB_ = sA_ + (uint32_t)B_OFF                         \
                                 + (uint32_t)(wn * 64 * RB) + laneB;           \
            const uint32_t kb_ = (uint32_t)(ks) * 32u;  /* 16 halves */        \
            _Pragma("unroll")                                                  \
            for (int mt = 0; mt < 4; mt++)                                     \
                ldsm4(AF[mt], aB_ + (uint32_t)(mt * 16 * RB) + kb_);           \
            _Pragma("unroll")                                                  \
            for (int p = 0; p < 4; p++)   /* p covers n = p*16 .. p*16+15 */   \
                ldsm4(BF[p], bB_ + (uint32_t)(p * 16 * RB) + kb_);             \
        } while (0)

    // BF[p] regs: r0=(n0-7,k0) r1=(n0-7,k8) r2=(n8-15,k0) r3=(n8-15,k8)
    #define DOMMA(AF, BF)                                                      \
        do {                                                                   \
            _Pragma("unroll")                                                  \
            for (int mt = 0; mt < 4; mt++) {                                   \
                _Pragma("unroll")                                              \
                for (int nt = 0; nt < 8; nt++) {                               \
                    uint32_t b0_ = BF[nt >> 1][(nt & 1) * 2 + 0];              \
                    uint32_t b1_ = BF[nt >> 1][(nt & 1) * 2 + 1];              \
                    mma16(acc[mt][nt], AF[mt], b0_, b1_);                      \
                }                                                              \
            }                                                                  \
        } while (0)

    issue(0);
    issue(1);
    asm volatile("cp.async.wait_group 1;" ::: "memory");   // my g0 done
    __syncthreads();                                       // everyone's g0 visible
    issue(2);
    LDFRAG(0, 0, af0, bf0);

    for (int c = 0; c < NCH; c++) {
        LDFRAG(c, 1, af1, bf1);  DOMMA(af0, bf0);
        LDFRAG(c, 2, af0, bf0);  DOMMA(af1, bf1);
        LDFRAG(c, 3, af1, bf1);  DOMMA(af0, bf0);
        if (c + 1 < NCH) {
            asm volatile("cp.async.wait_group 1;" ::: "memory");  // g(c+1) done (mine)
            __syncthreads();                 // publish g(c+1); stage c reads done
            if (c + 3 < NCH) issue(c + 3);
            else asm volatile("cp.async.commit_group;" ::: "memory");
            LDFRAG(c + 1, 0, af0, bf0);      // safe: after barrier
            DOMMA(af1, bf1);                 // ks3 of chunk c
        } else {
            DOMMA(af1, bf1);
        }
    }

    // ---- epilogue ----
    #pragma unroll
    for (int mt = 0; mt < 4; mt++) {
        int m = bm + wm * 64 + mt * 16 + lr;
        if (HALF_OUT) {
            __half* crow = (__half*)Cv + (size_t)m * N_TOT + bn + wn * 64;
            #pragma unroll
            for (int nt = 0; nt < 8; nt++) {
                int nf = nt * 8 + lc * 2;
                *(__half2*)(crow + nf) =
                    __floats2half2_rn(acc[mt][nt][0], acc[mt][nt][1]);
                *(__half2*)(crow + nf + (size_t)8 * N_TOT) =
                    __floats2half2_rn(acc[mt][nt][2], acc[mt][nt][3]);
            }
        } else {
            float* crow = (float*)Cv + (size_t)m * N_TOT + bn + wn * 64;
            #pragma unroll
            for (int nt = 0; nt < 8; nt++) {
                int nf = nt * 8 + lc * 2;
                *(float2*)(crow + nf) = make_float2(acc[mt][nt][0], acc[mt][nt][1]);
                *(float2*)(crow + nf + (size_t)8 * N_TOT) =
                    make_float2(acc[mt][nt][2], acc[mt][nt][3]);
            }
        }
    }
    #undef LDFRAG
    #undef DOMMA
}

// ---------------- fp32 -> fp16 convert (8 elems/thread) ----------------
__global__ void f2h_kernel(const float4* __restrict__ in, uint4* __restrict__ out)
{
    int i = blockIdx.x * 256 + threadIdx.x;
    float4 a = in[2 * i], b = in[2 * i + 1];
    __half2 h0 = __floats2half2_rn(a.x, a.y);
    __half2 h1 = __floats2half2_rn(a.z, a.w);
    __half2 h2 = __floats2half2_rn(b.x, b.y);
    __half2 h3 = __floats2half2_rn(b.z, b.w);
    uint4 o;
    o.x = *(uint32_t*)&h0; o.y = *(uint32_t*)&h1;
    o.z = *(uint32_t*)&h2; o.w = *(uint32_t*)&h3;
    out[i] = o;
}

// ---- 5-tap Gaussian window, per-head shift {0,-1,+1,0}x2; fp16 in/out -------
__global__ void conv_h_kernel(const __half* __restrict__ V, __half* __restrict__ Vc)
{
    int idx = blockIdx.x * blockDim.x + threadIdx.x;   // M_TOT*64 threads
    int c8  = idx & 63;          // 8-half group (512/8)
    int m   = idx >> 6;
    int s   = m & 4095;
    int mb0 = m - s;
    int hm  = (c8 >> 3) & 3;     // head = c8*8/64 = c8>>3
    int shift = (hm == 1) ? -1 : ((hm == 2) ? 1 : 0);

    const float F[5] = {0.05399096651318806f, 0.24197072451914337f,
                        0.3989422804014327f,  0.24197072451914337f,
                        0.05399096651318806f};

    float a[8];
    #pragma unroll
    for (int e = 0; e < 8; e++) a[e] = 0.0f;

    const uint4* V4 = (const uint4*)V;
    #pragma unroll
    for (int j = 0; j < 5; j++) {
        int ss = s + shift + j - 2;
        if (ss >= 0 && ss < 4096) {
            uint4 v = V4[(size_t)(mb0 + ss) * 64 + c8];
            __half2 p0 = *(__half2*)&v.x, p1 = *(__half2*)&v.y;
            __half2 p2 = *(__half2*)&v.z, p3 = *(__half2*)&v.w;
            float2 f0 = __half22float2(p0), f1 = __half22float2(p1);
            float2 f2 = __half22float2(p2), f3 = __half22float2(p3);
            a[0] += F[j] * f0.x; a[1] += F[j] * f0.y;
            a[2] += F[j] * f1.x; a[3] += F[j] * f1.y;
            a[4] += F[j] * f2.x; a[5] += F[j] * f2.y;
            a[6] += F[j] * f3.x; a[7] += F[j] * f3.y;
        }
    }
    __half2 o0 = __floats2half2_rn(a[0], a[1]);
    __half2 o1 = __floats2half2_rn(a[2], a[3]);
    __half2 o2 = __floats2half2_rn(a[4], a[5]);
    __half2 o3 = __floats2half2_rn(a[6], a[7]);
    uint4 o;
    o.x = *(uint32_t*)&o0; o.y = *(uint32_t*)&o1;
    o.z = *(uint32_t*)&o2; o.w = *(uint32_t*)&o3;
    ((uint4*)Vc)[idx] = o;
}

// ---------------- launcher ----------------
extern "C" void kernel_launch(void* const* d_in, const int* in_sizes, int n_in,
                              void* d_out, int out_size)
{
    const float* values = (const float*)d_in[0];
    const float* win    = (const float*)d_in[3];
    const float* wout   = (const float*)d_in[4];
    float*       out    = (float*)d_out;

    __half *pVh, *pV, *pVc, *pWa, *pWb;
    cudaGetSymbolAddress((void**)&pVh, g_Vh);
    cudaGetSymbolAddress((void**)&pV,  g_V);
    cudaGetSymbolAddress((void**)&pVc, g_Vc);
    cudaGetSymbolAddress((void**)&pWa, g_Wa);
    cudaGetSymbolAddress((void**)&pWb, g_Wb);

    cudaFuncSetAttribute(gemm_h16<true>,
                         cudaFuncAttributeMaxDynamicSharedMemorySize, SMEM_BYTES);
    cudaFuncSetAttribute(gemm_h16<false>,
                         cudaFuncAttributeMaxDynamicSharedMemorySize, SMEM_BYTES);

    dim3 grid(N_TOT / BN, M_TOT / BM);   // (4, 256)

    // converts: values 16M elems -> 2M threads; weights 256K -> 32K threads
    f2h_kernel<<<(M_TOT * K_TOT / 8) / 256, 256>>>((const float4*)values, (uint4*)pVh);
    f2h_kernel<<<(N_TOT * K_TOT / 8) / 256, 256>>>((const float4*)win,  (uint4*)pWa);
    f2h_kernel<<<(N_TOT * K_TOT / 8) / 256, 256>>>((const float4*)wout, (uint4*)pWb);

    gemm_h16<true ><<<grid, NTH, SMEM_BYTES>>>(pVh, pWa, pV);
    conv_h_kernel<<<(M_TOT * 64) / 256, 256>>>(pV, pVc);
    gemm_h16<false><<<grid, NTH, SMEM_BYTES>>>(pVc, pWb, out);
}

// round 15
// speedup vs baseline: 2.9117x; 1.0041x over previous
#include <cuda_runtime.h>
#include <cuda_fp16.h>
#include <cstdint>

// Shapes (fixed): B=8, S=4096, E=512 -> M=32768, N=K=512
#define M_TOT 32768
#define N_TOT 512
#define K_TOT 512

#define BM 128
#define BN 128
#define BK 64                 // halves; 4 k-slices of k16 per chunk
#define NTH 128               // 4 warps, 2(m) x 2(n), warp tile 64x64
#define NCH (K_TOT / BK)      // 8
#define NSTAGE 3

// smem rows: 64 data halves (128B) + 8 pad halves (16B) = 144B/row.
#define RB 144
#define B_OFF (128 * RB)
#define STG_B (2 * 128 * RB)              // 36864 B / stage
#define SMEM_BYTES (NSTAGE * STG_B)       // 110592 B -> 2 CTAs/SM

// ---------------- scratch (device globals: sanctioned no-alloc path) ----------
__device__ __half g_Vh[(size_t)M_TOT * K_TOT];
__device__ __half g_V [(size_t)M_TOT * N_TOT];
__device__ __half g_Vc[(size_t)M_TOT * N_TOT];
__device__ __half g_Wa[(size_t)N_TOT * K_TOT];
__device__ __half g_Wb[(size_t)N_TOT * K_TOT];

__device__ __forceinline__ uint32_t smem_u32(const void* p) {
    uint32_t a;
    asm("{ .reg .u64 t; cvta.to.shared.u64 t, %1; cvt.u32.u64 %0, t; }" : "=r"(a) : "l"(p));
    return a;
}
__device__ __forceinline__ void cp16(uint32_t saddr, const void* gptr) {
    asm volatile("cp.async.cg.shared.global [%0], [%1], 16;"
                 :: "r"(saddr), "l"(gptr) : "memory");
}
__device__ __forceinline__ void ldsm4(uint32_t* r, uint32_t addr) {
    asm volatile("ldmatrix.sync.aligned.m8n8.x4.shared.b16 {%0,%1,%2,%3}, [%4];"
                 : "=r"(r[0]), "=r"(r[1]), "=r"(r[2]), "=r"(r[3]) : "r"(addr));
}
__device__ __forceinline__ void mma16(float* c, const uint32_t* a,
                                      uint32_t b0, uint32_t b1) {
    asm volatile(
        "mma.sync.aligned.m16n8k16.row.col.f32.f16.f16.f32 "
        "{%0,%1,%2,%3}, {%4,%5,%6,%7}, {%8,%9}, {%0,%1,%2,%3};"
        : "+f"(c[0]), "+f"(c[1]), "+f"(c[2]), "+f"(c[3])
        : "r"(a[0]), "r"(a[1]), "r"(a[2]), "r"(a[3]), "r"(b0), "r"(b1));
}

// C[m,n] = sum_k A[m,k]*B[n,k]; A,B fp16 row-major [.,K]; fp32 acc.
// 64x64 warp tiles, 2 CTAs/SM, static double-buffered fragments,
// LDSM(next slice) interleaved between MMA rows of the current slice.
template <bool HALF_OUT>
__global__ __launch_bounds__(NTH, 2)
void gemm_h16(const __half* __restrict__ A,
              const __half* __restrict__ B,
              void* __restrict__ Cv)
{
    extern __shared__ char sm[];
    const uint32_t sb = smem_u32(sm);
    const int tid  = threadIdx.x;
    const int wid  = tid >> 5;
    const int lane = tid & 31;
    const int wm   = wid >> 1;
    const int wn   = wid & 1;
    const int lr   = lane >> 2;
    const int lc   = lane & 3;
    const int bm   = blockIdx.y * BM;
    const int bn   = blockIdx.x * BN;
    const int grp  = lane >> 3;
    const int lr8  = lane & 7;

    const uint4* Ag = (const uint4*)(A + (size_t)bm * K_TOT);
    const uint4* Bg = (const uint4*)(B + (size_t)bn * K_TOT);

    const uint32_t laneA = (uint32_t)(((grp & 1) * 8 + lr8) * RB + (grp >> 1) * 16);
    const uint32_t laneB = (uint32_t)(((grp >> 1) * 8 + lr8) * RB + (grp & 1) * 16);

    auto issue = [&](int c) {
        const int s = c % NSTAGE;
        const uint32_t sa  = sb + (uint32_t)(s * STG_B);
        const uint32_t sbB = sa + (uint32_t)B_OFF;
        #pragma unroll
        for (int i = 0; i < 8; i++) {
            int f = tid + i * NTH, m = f >> 3, q = f & 7;
            cp16(sa + (uint32_t)(m * RB + q * 16),
                 Ag + (size_t)m * (K_TOT / 8) + c * 8 + q);
        }
        #pragma unroll
        for (int i = 0; i < 8; i++) {
            int f = tid + i * NTH, n = f >> 3, q = f & 7;
            cp16(sbB + (uint32_t)(n * RB + q * 16),
                 Bg + (size_t)n * (K_TOT / 8) + c * 8 + q);
        }
        asm volatile("cp.async.commit_group;" ::: "memory");
    };

    uint32_t af0[4][4], bf0[4][4];
    uint32_t af1[4][4], bf1[4][4];

    float acc[4][8][4];
    #pragma unroll
    for (int a = 0; a < 4; a++)
        #pragma unroll
        for (int b = 0; b < 8; b++)
            #pragma unroll
            for (int r = 0; r < 4; r++) acc[a][b][r] = 0.0f;

    // fragment base addresses for (chunk, slice)
    #define ABASE(c, ks) (sb + (uint32_t)(((c) % NSTAGE) * STG_B)               \
                          + (uint32_t)(wm * 64 * RB) + laneA + (uint32_t)(ks) * 32u)
    #define BBASE(c, ks) (sb + (uint32_t)(((c) % NSTAGE) * STG_B) + (uint32_t)B_OFF \
                          + (uint32_t)(wn * 64 * RB) + laneB + (uint32_t)(ks) * 32u)

    #define MMAROW(AF, BF, mt)                                                 \
        do {                                                                   \
            _Pragma("unroll")                                                  \
            for (int nt = 0; nt < 8; nt++) {                                   \
                uint32_t b0_ = BF[nt >> 1][(nt & 1) * 2 + 0];                  \
                uint32_t b1_ = BF[nt >> 1][(nt & 1) * 2 + 1];                  \
                mma16(acc[mt][nt], AF[mt], b0_, b1_);                          \
            }                                                                  \
        } while (0)

    // consume (CA,CB); prefetch slice (cn,ksn) into (NA,NB), interleaved
    #define SLICE_INT(CA, CB, cn, ksn, NA, NB)                                 \
        do {                                                                   \
            const uint32_t aB_ = ABASE(cn, ksn);                               \
            const uint32_t bB_ = BBASE(cn, ksn);                               \
            ldsm4(NA[0], aB_);                                                 \
            ldsm4(NA[1], aB_ + (uint32_t)(16 * RB));                           \
            MMAROW(CA, CB, 0);                                                 \
            ldsm4(NA[2], aB_ + (uint32_t)(32 * RB));                           \
            ldsm4(NA[3], aB_ + (uint32_t)(48 * RB));                           \
            MMAROW(CA, CB, 1);                                                 \
            ldsm4(NB[0], bB_);                                                 \
            ldsm4(NB[1], bB_ + (uint32_t)(16 * RB));                           \
            MMAROW(CA, CB, 2);                                                 \
            ldsm4(NB[2], bB_ + (uint32_t)(32 * RB));                           \
            ldsm4(NB[3], bB_ + (uint32_t)(48 * RB));                           \
            MMAROW(CA, CB, 3);                                                 \
        } while (0)

    #define SLICE_LAST(CA, CB)                                                 \
        do { MMAROW(CA, CB, 0); MMAROW(CA, CB, 1);                             \
             MMAROW(CA, CB, 2); MMAROW(CA, CB, 3); } while (0)

    #define PF0(c, AF, BF)                                                     \
        do {                                                                   \
            const uint32_t aB_ = ABASE(c, 0);                                  \
            const uint32_t bB_ = BBASE(c, 0);                                  \
            _Pragma("unroll")                                                  \
            for (int mt = 0; mt < 4; mt++)                                     \
                ldsm4(AF[mt], aB_ + (uint32_t)(mt * 16 * RB));                 \
            _Pragma("unroll")                                                  \
            for (int p = 0; p < 4; p++)                                        \
                ldsm4(BF[p], bB_ + (uint32_t)(p * 16 * RB));                   \
        } while (0)

    // prologue
    issue(0);
    issue(1);
    asm volatile("cp.async.wait_group 1;" ::: "memory");   // my g0 done
    __syncthreads();                                       // everyone's g0 visible
    issue(2);
    PF0(0, af0, bf0);

    for (int c = 0; c < NCH; c++) {
        SLICE_INT(af0, bf0, c, 1, af1, bf1);   // consume s0, prefetch s1
        SLICE_INT(af1, bf1, c, 2, af0, bf0);   // consume s1, prefetch s2
        SLICE_INT(af0, bf0, c, 3, af1, bf1);   // consume s2, prefetch s3
        // all reads of stage c done (s3 fragments are in registers)
        if (c + 1 < NCH) {
            // committed groups: 0..c+2; wait_group 1 -> g(c+1) done (mine)
            asm volatile("cp.async.wait_group 1;" ::: "memory");
            __syncthreads();                   // publish g(c+1); stage c free
            if (c + 3 < NCH) issue(c + 3);     // overwrite stage c
            else asm volatile("cp.async.commit_group;" ::: "memory");
            SLICE_INT(af1, bf1, c + 1, 0, af0, bf0);  // consume s3, prefetch next s0
        } else {
            SLICE_LAST(af1, bf1);
        }
    }

    // ---- epilogue ----
    #pragma unroll
    for (int mt = 0; mt < 4; mt++) {
        int m = bm + wm * 64 + mt * 16 + lr;
        if (HALF_OUT) {
            __half* crow = (__half*)Cv + (size_t)m * N_TOT + bn + wn * 64;
            #pragma unroll
            for (int nt = 0; nt < 8; nt++) {
                int nf = nt * 8 + lc * 2;
                *(__half2*)(crow + nf) =
                    __floats2half2_rn(acc[mt][nt][0], acc[mt][nt][1]);
                *(__half2*)(crow + nf + (size_t)8 * N_TOT) =
                    __floats2half2_rn(acc[mt][nt][2], acc[mt][nt][3]);
            }
        } else {
            float* crow = (float*)Cv + (size_t)m * N_TOT + bn + wn * 64;
            #pragma unroll
            for (int nt = 0; nt < 8; nt++) {
                int nf = nt * 8 + lc * 2;
                *(float2*)(crow + nf) = make_float2(acc[mt][nt][0], acc[mt][nt][1]);
                *(float2*)(crow + nf + (size_t)8 * N_TOT) =
                    make_float2(acc[mt][nt][2], acc[mt][nt][3]);
            }
        }
    }
    #undef ABASE
    #undef BBASE
    #undef MMAROW
    #undef SLICE_INT
    #undef SLICE_LAST
    #undef PF0
}

// ---------------- fp32 -> fp16 convert, 16 elems/thread (MLP 4) --------------
__global__ void f2h_kernel(const float4* __restrict__ in, uint4* __restrict__ out)
{
    int i = blockIdx.x * 256 + threadIdx.x;
    float4 a = in[4 * i + 0], b = in[4 * i + 1];
    float4 c = in[4 * i + 2], d = in[4 * i + 3];
    __half2 h0 = __floats2half2_rn(a.x, a.y), h1 = __floats2half2_rn(a.z, a.w);
    __half2 h2 = __floats2half2_rn(b.x, b.y), h3 = __floats2half2_rn(b.z, b.w);
    __half2 h4 = __floats2half2_rn(c.x, c.y), h5 = __floats2half2_rn(c.z, c.w);
    __half2 h6 = __floats2half2_rn(d.x, d.y), h7 = __floats2half2_rn(d.z, d.w);
    uint4 o0, o1;
    o0.x = *(uint32_t*)&h0; o0.y = *(uint32_t*)&h1;
    o0.z = *(uint32_t*)&h2; o0.w = *(uint32_t*)&h3;
    o1.x = *(uint32_t*)&h4; o1.y = *(uint32_t*)&h5;
    o1.z = *(uint32_t*)&h6; o1.w = *(uint32_t*)&h7;
    out[2 * i + 0] = o0;
    out[2 * i + 1] = o1;
}

// ---- 5-tap Gaussian window, per-head shift {0,-1,+1,0}x2; fp16 in/out -------
__global__ void conv_h_kernel(const __half* __restrict__ V, __half* __restrict__ Vc)
{
    int idx = blockIdx.x * blockDim.x + threadIdx.x;   // M_TOT*64 threads
    int c8  = idx & 63;
    int m   = idx >> 6;
    int s   = m & 4095;
    int mb0 = m - s;
    int hm  = (c8 >> 3) & 3;
    int shift = (hm == 1) ? -1 : ((hm == 2) ? 1 : 0);

    const float F[5] = {0.05399096651318806f, 0.24197072451914337f,
                        0.3989422804014327f,  0.24197072451914337f,
                        0.05399096651318806f};

    float a[8];
    #pragma unroll
    for (int e = 0; e < 8; e++) a[e] = 0.0f;

    const uint4* V4 = (const uint4*)V;
    #pragma unroll
    for (int j = 0; j < 5; j++) {
        int ss = s + shift + j - 2;
        if (ss >= 0 && ss < 4096) {
            uint4 v = V4[(size_t)(mb0 + ss) * 64 + c8];
            __half2 p0 = *(__half2*)&v.x, p1 = *(__half2*)&v.y;
            __half2 p2 = *(__half2*)&v.z, p3 = *(__half2*)&v.w;
            float2 f0 = __half22float2(p0), f1 = __half22float2(p1);
            float2 f2 = __half22float2(p2), f3 = __half22float2(p3);
            a[0] += F[j] * f0.x; a[1] += F[j] * f0.y;
            a[2] += F[j] * f1.x; a[3] += F[j] * f1.y;
            a[4] += F[j] * f2.x; a[5] += F[j] * f2.y;
            a[6] += F[j] * f3.x; a[7] += F[j] * f3.y;
        }
    }
    __half2 o0 = __floats2half2_rn(a[0], a[1]);
    __half2 o1 = __floats2half2_rn(a[2], a[3]);
    __half2 o2 = __floats2half2_rn(a[4], a[5]);
    __half2 o3 = __floats2half2_rn(a[6], a[7]);
    uint4 o;
    o.x = *(uint32_t*)&o0; o.y = *(uint32_t*)&o1;
    o.z = *(uint32_t*)&o2; o.w = *(uint32_t*)&o3;
    ((uint4*)Vc)[idx] = o;
}

// ---------------- launcher ----------------
extern "C" void kernel_launch(void* const* d_in, const int* in_sizes, int n_in,
                              void* d_out, int out_size)
{
    const float* values = (const float*)d_in[0];
    const float* win    = (const float*)d_in[3];
    const float* wout   = (const float*)d_in[4];
    float*       out    = (float*)d_out;

    __half *pVh, *pV, *pVc, *pWa, *pWb;
    cudaGetSymbolAddress((void**)&pVh, g_Vh);
    cudaGetSymbolAddress((void**)&pV,  g_V);
    cudaGetSymbolAddress((void**)&pVc, g_Vc);
    cudaGetSymbolAddress((void**)&pWa, g_Wa);
    cudaGetSymbolAddress((void**)&pWb, g_Wb);

    cudaFuncSetAttribute(gemm_h16<true>,
                         cudaFuncAttributeMaxDynamicSharedMemorySize, SMEM_BYTES);
    cudaFuncSetAttribute(gemm_h16<false>,
                         cudaFuncAttributeMaxDynamicSharedMemorySize, SMEM_BYTES);

    dim3 grid(N_TOT / BN, M_TOT / BM);   // (4, 256)

    f2h_kernel<<<(M_TOT * K_TOT / 16) / 256, 256>>>((const float4*)values, (uint4*)pVh);
    f2h_kernel<<<(N_TOT * K_TOT / 16) / 256, 256>>>((const float4*)win,  (uint4*)pWa);
    f2h_kernel<<<(N_TOT * K_TOT / 16) / 256, 256>>>((const float4*)wout, (uint4*)pWb);

    gemm_h16<true ><<<grid, NTH, SMEM_BYTES>>>(pVh, pWa, pV);
    conv_h_kernel<<<(M_TOT * 64) / 256, 256>>>(pV, pVc);
    gemm_h16<false><<<grid, NTH, SMEM_BYTES>>>(pVc, pWb, out);
}